// round 17
// baseline (speedup 1.0000x reference)
#include <cuda_runtime.h>
#include <cstdint>
#include <math.h>

#define S_LEN 2048
#define HID 1024
#define NH 16
#define HD 64
#define GN 1024
#define GK 1024

__device__ float g_q[S_LEN * HID];
__device__ float g_k[S_LEN * HID];
__device__ float g_v[S_LEN * HID];
__device__ float g_att[S_LEN * HID];
__device__ float g_xc[S_LEN * HID];
__device__ float g_wq[HID * HID];
__device__ float g_wk[HID * HID];
__device__ float g_wv[HID * HID];
__device__ float g_wo[HID * HID];

__device__ __forceinline__ uint32_t f2tf(float x) {
    uint32_t u;
    asm("cvt.rna.tf32.f32 %0, %1;" : "=r"(u) : "f"(x));
    return u;
}

__device__ __forceinline__ void mma_tf32(float* c, const uint32_t* a, uint32_t b0,
                                         uint32_t b1) {
    asm volatile(
        "mma.sync.aligned.m16n8k8.row.col.f32.tf32.tf32.f32 "
        "{%0,%1,%2,%3}, {%4,%5,%6,%7}, {%8,%9}, {%0,%1,%2,%3};"
        : "+f"(c[0]), "+f"(c[1]), "+f"(c[2]), "+f"(c[3])
        : "r"(a[0]), "r"(a[1]), "r"(a[2]), "r"(a[3]), "r"(b0), "r"(b1));
}

__device__ __forceinline__ void cp16(uint32_t dst, const float* src) {
    asm volatile("cp.async.cg.shared.global [%0], [%1], 16;" ::"r"(dst), "l"(src));
}
__device__ __forceinline__ void cp_commit() {
    asm volatile("cp.async.commit_group;");
}
template <int N>
__device__ __forceinline__ void cp_wait() {
    asm volatile("cp.async.wait_group %0;" ::"n"(N));
}

// ---------------------------------------------------------------------------
// Pre-convert inputs to tf32 (rna), stored as fp32 bit patterns.
// ---------------------------------------------------------------------------
__global__ __launch_bounds__(256) void cvt_inputs(
    const float* __restrict__ x, const float* __restrict__ wq,
    const float* __restrict__ wk, const float* __restrict__ wv,
    const float* __restrict__ wo, float* __restrict__ xc, float* __restrict__ wqc,
    float* __restrict__ wkc, float* __restrict__ wvc, float* __restrict__ woc) {
    int i = blockIdx.x * 256 + threadIdx.x;
    const float* src;
    float* dst;
    int off;
    if (i < 524288) {
        src = x; dst = xc; off = i;
    } else {
        int r = i - 524288;
        int w = r >> 18;
        off = r & 262143;
        src = (w == 0) ? wq : (w == 1) ? wk : (w == 2) ? wv : wo;
        dst = (w == 0) ? wqc : (w == 1) ? wkc : (w == 2) ? wvc : woc;
    }
    float4 v = *(const float4*)(src + (size_t)off * 4);
    uint4 o = make_uint4(f2tf(v.x), f2tf(v.y), f2tf(v.z), f2tf(v.w));
    *(uint4*)(dst + (size_t)off * 4) = o;
}

// ---------------------------------------------------------------------------
// cp.async tf32 GEMM: BMx128 tile (BM=128 or 64), BK=16, 3-stage pipeline,
// 256 threads. BM=128: warp tile 64x32. BM=64: warp tile 32x32 (2 m-frags),
// grid doubles -> 2-3 blocks/SM resident.
// ---------------------------------------------------------------------------
template <bool ROUND_C, int NT, int BM>
__device__ __forceinline__ void gemm_body(const float* __restrict__ A,
                                          const float* __restrict__ B,
                                          float* __restrict__ C, int row0, int col0) {
    constexpr int AW = BM * 16;        // A words per stage
    constexpr int MT = BM / 32;        // m-frags per warp
    __shared__ uint32_t As[3][AW];
    __shared__ uint32_t Bs[3][2048];

    const int tid = threadIdx.x;
    const int lane = tid & 31;
    const int w = tid >> 5;
    const int gid = lane >> 2;
    const int tg = lane & 3;
    const int warp_m = (w & 1) * (BM / 2);
    const int warp_n = (w >> 1) * 32;

    // A loader: BM=128 -> 2 cp16/thread; BM=64 -> 1 cp16/thread
    const int ra = (BM == 128) ? (tid >> 1) : (tid >> 2);
    const int ca = (BM == 128) ? ((tid & 1) * 2) : (tid & 3);
    const int rb = tid >> 4, cb = (tid & 15) * 2;
    const float* pa = A + (size_t)(row0 + ra) * GK + ca * 4;
    const float* pb = B + (size_t)rb * GN + col0 + cb * 4;
    const int sa0 = ra * 16 + ((ca ^ ((ra >> 1) & 3)) << 2);
    const int sa1 = ra * 16 + (((ca + 1) ^ ((ra >> 1) & 3)) << 2);  // BM=128 only
    const int sb0 = rb * 128 + ((cb ^ (2 * (rb & 3))) << 2);
    const int sb1 = rb * 128 + (((cb + 1) ^ (2 * (rb & 3))) << 2);
    const uint32_t asb = (uint32_t)__cvta_generic_to_shared(&As[0][0]);
    const uint32_t bsb = (uint32_t)__cvta_generic_to_shared(&Bs[0][0]);

    float c[MT][4][4];
#pragma unroll
    for (int i = 0; i < MT; i++)
#pragma unroll
        for (int j = 0; j < 4; j++)
#pragma unroll
            for (int r = 0; r < 4; r++) c[i][j][r] = 0.f;

#define ISSUE(s)                                               \
    {                                                          \
        cp16(asb + ((s)*AW + sa0) * 4, pa);                    \
        if (BM == 128) cp16(asb + ((s)*AW + sa1) * 4, pa + 4); \
        cp16(bsb + ((s)*2048 + sb0) * 4, pb);                  \
        cp16(bsb + ((s)*2048 + sb1) * 4, pb + 4);              \
        cp_commit();                                           \
        pa += 16;                                              \
        pb += (size_t)16 * GN;                                 \
    }

#define COMPUTE(s)                                                              \
    {                                                                           \
        _Pragma("unroll") for (int ks = 0; ks < 2; ks++) {                      \
            uint32_t a[MT][4], b[4][2];                                         \
            _Pragma("unroll") for (int mt = 0; mt < MT; mt++) {                 \
                int m0 = warp_m + mt * 16 + gid;                                \
                int m1 = m0 + 8;                                                \
                a[mt][0] = As[s][m0 * 16 + (((2 * ks) ^ ((m0 >> 1) & 3)) << 2) + tg]; \
                a[mt][1] = As[s][m1 * 16 + (((2 * ks) ^ ((m1 >> 1) & 3)) << 2) + tg]; \
                a[mt][2] = As[s][m0 * 16 + (((2 * ks + 1) ^ ((m0 >> 1) & 3)) << 2) + tg]; \
                a[mt][3] = As[s][m1 * 16 + (((2 * ks + 1) ^ ((m1 >> 1) & 3)) << 2) + tg]; \
            }                                                                   \
            _Pragma("unroll") for (int nt = 0; nt < 4; nt++) {                  \
                int n = warp_n + nt * 8 + gid;                                  \
                int nc = ((n >> 2) ^ (2 * tg)) << 2;                            \
                b[nt][0] = Bs[s][(tg + 8 * ks) * 128 + nc + (n & 3)];           \
                b[nt][1] = Bs[s][(tg + 4 + 8 * ks) * 128 + nc + (n & 3)];       \
            }                                                                   \
            _Pragma("unroll") for (int mt = 0; mt < MT; mt++)                   \
                _Pragma("unroll") for (int nt = 0; nt < 4; nt++)                \
                    mma_tf32(c[mt][nt], a[mt], b[nt][0], b[nt][1]);             \
        }                                                                       \
    }

    ISSUE(0);
    ISSUE(1);

    constexpr int T0 = ((NT - 4) / 3) * 3;
#pragma unroll 1
    for (int t = 0; t < T0; t += 3) {
        cp_wait<1>();
        __syncthreads();
        ISSUE(2);
        COMPUTE(0);
        cp_wait<1>();
        __syncthreads();
        ISSUE(0);
        COMPUTE(1);
        cp_wait<1>();
        __syncthreads();
        ISSUE(1);
        COMPUTE(2);
    }
#pragma unroll
    for (int t = T0; t < NT; t++) {
        const int st = t % 3;
        if (t + 2 < NT) {
            cp_wait<1>();
            __syncthreads();
            if ((t + 2) % 3 == 0) ISSUE(0);
            if ((t + 2) % 3 == 1) ISSUE(1);
            if ((t + 2) % 3 == 2) ISSUE(2);
        } else if (t + 1 < NT) {
            cp_wait<1>();
            __syncthreads();
        } else {
            cp_wait<0>();
            __syncthreads();
        }
        if (st == 0) COMPUTE(0);
        if (st == 1) COMPUTE(1);
        if (st == 2) COMPUTE(2);
    }

#pragma unroll
    for (int mt = 0; mt < MT; mt++)
#pragma unroll
        for (int nt = 0; nt < 4; nt++) {
            int row = row0 + warp_m + mt * 16 + gid;
            int col = col0 + warp_n + nt * 8 + tg * 2;
            if (ROUND_C) {
                *(uint2*)&C[(size_t)row * GN + col] =
                    make_uint2(f2tf(c[mt][nt][0]), f2tf(c[mt][nt][1]));
                *(uint2*)&C[(size_t)(row + 8) * GN + col] =
                    make_uint2(f2tf(c[mt][nt][2]), f2tf(c[mt][nt][3]));
            } else {
                *(float2*)&C[(size_t)row * GN + col] =
                    make_float2(c[mt][nt][0], c[mt][nt][1]);
                *(float2*)&C[(size_t)(row + 8) * GN + col] =
                    make_float2(c[mt][nt][2], c[mt][nt][3]);
            }
        }
#undef ISSUE
#undef COMPUTE
}

__global__ __launch_bounds__(256) void gemm_out(const float* __restrict__ A,
                                                const float* __restrict__ B,
                                                float* __restrict__ C) {
    gemm_body<false, 64, 64>(A, B, C, blockIdx.y * 64, blockIdx.x * 128);
}

__global__ __launch_bounds__(256) void gemm_qkv(const float* __restrict__ A,
                                                const float* __restrict__ B0,
                                                const float* __restrict__ B1,
                                                const float* __restrict__ B2,
                                                float* __restrict__ C0,
                                                float* __restrict__ C1,
                                                float* __restrict__ C2) {
    int sel = blockIdx.x >> 3;
    const float* B = (sel == 0) ? B0 : (sel == 1) ? B1 : B2;
    float* C = (sel == 0) ? C0 : (sel == 1) ? C1 : C2;
    gemm_body<true, 64, 128>(A, B, C, blockIdx.y * 128, (blockIdx.x & 7) * 128);
}

// ---------------------------------------------------------------------------
// Tensor-core flash sparse attention (unchanged R16): 32-key chunks,
// cp.async double-buffered K/V natural layout, P via shuffles.
// ---------------------------------------------------------------------------
#define ACH 32

__global__ __launch_bounds__(128) void attn_mma(const float* __restrict__ Q,
                                                const float* __restrict__ Kg,
                                                const float* __restrict__ Vg,
                                                float* __restrict__ O) {
    __shared__ uint32_t Ks[2][ACH * 64];
    __shared__ uint32_t Vs[2][ACH * 64];

    const int tid = threadIdx.x;
    const int lane = tid & 31;
    const int w = tid >> 5;
    const int gid = lane >> 2;
    const int tg = lane & 3;
    const int wm = w * 16;
    const int q0 = blockIdx.x * 64;
    const int hb = blockIdx.y * HD;
    const unsigned FULL = 0xffffffffu;
    const uint32_t ksb = (uint32_t)__cvta_generic_to_shared(&Ks[0][0]);
    const uint32_t vsb = (uint32_t)__cvta_generic_to_shared(&Vs[0][0]);

    uint32_t qa[8][4];
    {
        const uint32_t* qp = (const uint32_t*)(Q + (size_t)(q0 + wm + gid) * HID + hb);
#pragma unroll
        for (int ks = 0; ks < 8; ks++) {
            qa[ks][0] = qp[ks * 8 + tg];
            qa[ks][1] = qp[8 * HID + ks * 8 + tg];
            qa[ks][2] = qp[ks * 8 + tg + 4];
            qa[ks][3] = qp[8 * HID + ks * 8 + tg + 4];
        }
    }

    float m[2] = {-1e30f, -1e30f}, lsum[2] = {0.f, 0.f};
    float o[8][4];
#pragma unroll
    for (int nt = 0; nt < 8; nt++)
#pragma unroll
        for (int r = 0; r < 4; r++) o[nt][r] = 0.f;

    const int c_start = max(0, q0 - 512);
    const int ng = (c_start + 511) >> 9;
    const int has_pro = (c_start > 0) ? 1 : 0;
    const int nch = ((q0 + 64 - c_start) >> 5) + has_pro;

#define ISSUE_CHUNK(ci)                                                         \
    {                                                                           \
        int b_ = (ci) & 1;                                                      \
        bool pro_ = has_pro && ((ci) == 0);                                     \
        int base_ = pro_ ? 0 : c_start + ((ci)-has_pro) * ACH;                  \
        _Pragma("unroll") for (int l = 0; l < 4; l++) {                         \
            int g = tid + l * 128;                                              \
            int jr = g >> 4, d4 = g & 15;                                       \
            int jg = pro_ ? ((jr < ng ? jr : 0) << 9) : (base_ + jr);           \
            int dw = jr * 64 + ((d4 ^ (jr & 15)) << 2);                         \
            cp16(ksb + (b_ * (ACH * 64) + dw) * 4,                              \
                 Kg + (size_t)jg * HID + hb + d4 * 4);                          \
            cp16(vsb + (b_ * (ACH * 64) + dw) * 4,                              \
                 Vg + (size_t)jg * HID + hb + d4 * 4);                          \
        }                                                                       \
        cp_commit();                                                            \
    }

    ISSUE_CHUNK(0);

    for (int ci = 0; ci < nch; ci++) {
        if (ci + 1 < nch) {
            ISSUE_CHUNK(ci + 1);
            cp_wait<1>();
        } else {
            cp_wait<0>();
        }
        __syncthreads();

        const int b = ci & 1;
        const bool pro = has_pro && (ci == 0);
        const int base = pro ? 0 : c_start + (ci - has_pro) * ACH;

        float s[4][4];
#pragma unroll
        for (int nt = 0; nt < 4; nt++)
#pragma unroll
            for (int r = 0; r < 4; r++) s[nt][r] = 0.f;

#pragma unroll
        for (int ks = 0; ks < 8; ks++) {
#pragma unroll
            for (int nt = 0; nt < 4; nt++) {
                int j = gid + 8 * nt;
                uint32_t b0 = Ks[b][j * 64 + (((2 * ks) ^ (j & 15)) << 2) + tg];
                uint32_t b1 = Ks[b][j * 64 + (((2 * ks + 1) ^ (j & 15)) << 2) + tg];
                mma_tf32(s[nt], qa[ks], b0, b1);
            }
        }

        uint32_t ps[4][4];
#pragma unroll
        for (int r = 0; r < 2; r++) {
            const int i = q0 + wm + gid + 8 * r;
            float rm = -1e30f;
#pragma unroll
            for (int nt = 0; nt < 4; nt++) {
#pragma unroll
                for (int dj = 0; dj < 2; dj++) {
                    int jj = 8 * nt + 2 * tg + dj;
                    bool valid;
                    if (pro) {
                        valid = jj < ng;
                    } else {
                        int j = base + jj;
                        valid = (j <= i) && ((i - j) <= 512 || (j & 511) == 0);
                    }
                    float x = valid ? s[nt][2 * r + dj] * 0.125f : -1e30f;
                    s[nt][2 * r + dj] = x;
                    rm = fmaxf(rm, x);
                }
            }
            rm = fmaxf(rm, __shfl_xor_sync(FULL, rm, 1));
            rm = fmaxf(rm, __shfl_xor_sync(FULL, rm, 2));
            float mn = fmaxf(m[r], rm);
            float scf = __expf(m[r] - mn);
            m[r] = mn;
            float rs = 0.f;
#pragma unroll
            for (int nt = 0; nt < 4; nt++) {
                float p0 = __expf(s[nt][2 * r] - mn);
                float p1 = __expf(s[nt][2 * r + 1] - mn);
                rs += p0 + p1;
                ps[nt][2 * r] = f2tf(p0);
                ps[nt][2 * r + 1] = f2tf(p1);
            }
#pragma unroll
            for (int nt = 0; nt < 8; nt++) {
                o[nt][2 * r] *= scf;
                o[nt][2 * r + 1] *= scf;
            }
            rs += __shfl_xor_sync(FULL, rs, 1);
            rs += __shfl_xor_sync(FULL, rs, 2);
            lsum[r] = lsum[r] * scf + rs;
        }

        const int L0 = (gid << 2) + (tg >> 1);
        const int L1 = L0 + 2;
        const bool hi = (tg & 1) != 0;
#pragma unroll
        for (int ks2 = 0; ks2 < 4; ks2++) {
            uint32_t v0 = __shfl_sync(FULL, ps[ks2][0], L0);
            uint32_t v1 = __shfl_sync(FULL, ps[ks2][1], L0);
            uint32_t v2 = __shfl_sync(FULL, ps[ks2][2], L0);
            uint32_t v3 = __shfl_sync(FULL, ps[ks2][3], L0);
            uint32_t w0 = __shfl_sync(FULL, ps[ks2][0], L1);
            uint32_t w1 = __shfl_sync(FULL, ps[ks2][1], L1);
            uint32_t w2 = __shfl_sync(FULL, ps[ks2][2], L1);
            uint32_t w3 = __shfl_sync(FULL, ps[ks2][3], L1);
            uint32_t pa[4];
            pa[0] = hi ? v1 : v0;
            pa[1] = hi ? v3 : v2;
            pa[2] = hi ? w1 : w0;
            pa[3] = hi ? w3 : w2;
            int j0 = 8 * ks2 + tg, j1 = j0 + 4;
#pragma unroll
            for (int nt = 0; nt < 8; nt++) {
                int d = gid + 8 * nt;
                int cch = d >> 2;
                uint32_t vb0 = Vs[b][j0 * 64 + ((cch ^ (j0 & 15)) << 2) + (d & 3)];
                uint32_t vb1 = Vs[b][j1 * 64 + ((cch ^ (j1 & 15)) << 2) + (d & 3)];
                mma_tf32(o[nt], pa, vb0, vb1);
            }
        }
        __syncthreads();
    }
#undef ISSUE_CHUNK

#pragma unroll
    for (int r = 0; r < 2; r++) {
        float inv = 1.0f / lsum[r];
        float* orow = O + (size_t)(q0 + wm + gid + 8 * r) * HID + hb;
#pragma unroll
        for (int nt = 0; nt < 8; nt++)
            *(uint2*)&orow[8 * nt + 2 * tg] =
                make_uint2(f2tf(o[nt][2 * r] * inv), f2tf(o[nt][2 * r + 1] * inv));
    }
}

// ---------------------------------------------------------------------------
extern "C" void kernel_launch(void* const* d_in, const int* in_sizes, int n_in,
                              void* d_out, int out_size) {
    const float* x   = (const float*)d_in[0];
    const float* w_q = (const float*)d_in[1];
    const float* w_k = (const float*)d_in[2];
    const float* w_v = (const float*)d_in[3];
    const float* w_o = (const float*)d_in[4];
    float* out = (float*)d_out;

    float *q, *k, *v, *att, *xc, *wq, *wk, *wv, *wo;
    cudaGetSymbolAddress((void**)&q, g_q);
    cudaGetSymbolAddress((void**)&k, g_k);
    cudaGetSymbolAddress((void**)&v, g_v);
    cudaGetSymbolAddress((void**)&att, g_att);
    cudaGetSymbolAddress((void**)&xc, g_xc);
    cudaGetSymbolAddress((void**)&wq, g_wq);
    cudaGetSymbolAddress((void**)&wk, g_wk);
    cudaGetSymbolAddress((void**)&wv, g_wv);
    cudaGetSymbolAddress((void**)&wo, g_wo);

    cvt_inputs<<<6144, 256>>>(x, w_q, w_k, w_v, w_o, xc, wq, wk, wv, wo);

    gemm_qkv<<<dim3(24, 16), 256>>>(xc, wq, wk, wv, q, k, v);

    attn_mma<<<dim3(S_LEN / 64, NH), 128>>>(q, k, v, att);

    gemm_out<<<dim3(8, 32), 256>>>(att, wo, out);
}